// round 16
// baseline (speedup 1.0000x reference)
#include <cuda_runtime.h>
#include <cuda_fp16.h>
#include <math.h>
#include <stdint.h>

// Problem constants
#define BB 2
#define TT 2048
#define HH 16
#define DD 64
#define CC 1024

// Scratch (device globals: allocation-free per harness rules)
__device__ float  g_qkv[BB * TT * 3 * CC];
__device__ __half g_q[BB * HH * TT * DD];
__device__ __half g_k[BB * HH * TT * DD];
__device__ __half g_v[BB * HH * TT * DD];
__device__ __half g_y[BB * TT * CC];
__device__ __half g_xr[BB * TT * CC];       // fp16-rounded x
__device__ __half g_war[3 * CC * CC];       // fp16-rounded w_attn
__device__ __half g_wpr[CC * CC];           // fp16-rounded w_proj

// ---------------------------------------------------------------------------
// mma / ldmatrix / async helpers (fp16, fp32 accumulate)
// ---------------------------------------------------------------------------
__device__ __forceinline__ void mma_f16(float* d,
    unsigned a0, unsigned a1, unsigned a2, unsigned a3,
    unsigned b0, unsigned b1)
{
    asm volatile(
        "mma.sync.aligned.m16n8k16.row.col.f32.f16.f16.f32 "
        "{%0,%1,%2,%3}, {%4,%5,%6,%7}, {%8,%9}, {%0,%1,%2,%3};\n"
        : "+f"(d[0]), "+f"(d[1]), "+f"(d[2]), "+f"(d[3])
        : "r"(a0), "r"(a1), "r"(a2), "r"(a3), "r"(b0), "r"(b1));
}

__device__ __forceinline__ void ldsm_x4(unsigned& r0, unsigned& r1,
                                        unsigned& r2, unsigned& r3, uint32_t a)
{
    asm volatile("ldmatrix.sync.aligned.m8n8.x4.shared.b16 {%0,%1,%2,%3}, [%4];"
                 : "=r"(r0), "=r"(r1), "=r"(r2), "=r"(r3) : "r"(a));
}
__device__ __forceinline__ void ldsm_x4_t(unsigned& r0, unsigned& r1,
                                          unsigned& r2, unsigned& r3, uint32_t a)
{
    asm volatile("ldmatrix.sync.aligned.m8n8.x4.trans.shared.b16 {%0,%1,%2,%3}, [%4];"
                 : "=r"(r0), "=r"(r1), "=r"(r2), "=r"(r3) : "r"(a));
}

__device__ __forceinline__ void cp16(uint32_t s, const void* g) {
    asm volatile("cp.async.cg.shared.global [%0], [%1], 16;\n" :: "r"(s), "l"(g));
}
__device__ __forceinline__ void cp_commit() {
    asm volatile("cp.async.commit_group;\n");
}
__device__ __forceinline__ void cp_wait0() {
    asm volatile("cp.async.wait_group 0;\n" ::: "memory");
}
__device__ __forceinline__ void cp_wait1() {
    asm volatile("cp.async.wait_group 1;\n" ::: "memory");
}

// ---------------------------------------------------------------------------
// Merged RN-round of x, w_attn, w_proj to fp16 (one launch).
// ---------------------------------------------------------------------------
#define N4_X  (BB * TT * CC / 4)
#define N4_WA (3 * CC * CC / 4)
#define N4_WP (CC * CC / 4)

__global__ void round_all_kernel(const float4* __restrict__ x,  __half2* __restrict__ xr,
                                 const float4* __restrict__ wa, __half2* __restrict__ war,
                                 const float4* __restrict__ wp, __half2* __restrict__ wpr)
{
    int i = blockIdx.x * blockDim.x + threadIdx.x;
    const float4* s; __half2* d; int j;
    if (i < N4_X)                 { s = x;  d = xr;  j = i; }
    else if (i < N4_X + N4_WA)    { s = wa; d = war; j = i - N4_X; }
    else if (i < N4_X + N4_WA + N4_WP) { s = wp; d = wpr; j = i - N4_X - N4_WA; }
    else return;
    float4 v = s[j];
    d[2 * j]     = __floats2half2_rn(v.x, v.y);
    d[2 * j + 1] = __floats2half2_rn(v.z, v.w);
}

// ---------------------------------------------------------------------------
// fp16 tensor-core GEMM: C[m][n] = sum_k A[m][k]*B[n][k]   (C = A*B^T)
// 128x128 block tile, BK=32, 256 threads (8 warps), warp tile 64x32.
// 3-stage cp.async pipeline (2 groups in flight), ldmatrix frags, fp32 acc.
// ---------------------------------------------------------------------------
#define GPH 40   // smem pitch in halves (80B): banks 20r%32 distinct per 8 rows
#define GSTG 3
#define GEMM_BUF (128 * GPH)                 // halves per matrix per stage
#define GEMM_SMEM_BYTES (2 * GSTG * GEMM_BUF * 2)

__global__ __launch_bounds__(256) void hgemm_abt(
    const __half* __restrict__ A, const __half* __restrict__ Bm,
    float* __restrict__ Cm, int M, int N, int K)
{
    extern __shared__ __align__(16) __half gsm[];
    __half* As = gsm;                        // [GSTG][GEMM_BUF]
    __half* Bs = gsm + GSTG * GEMM_BUF;      // [GSTG][GEMM_BUF]

    const int tid  = threadIdx.x;
    const int warp = tid >> 5;
    const int lane = tid & 31;
    const int g = lane >> 2;
    const int c = lane & 3;

    const int wm = (warp & 1) * 64;
    const int wn = (warp >> 1) * 32;

    const int bm = blockIdx.y * 128;
    const int bn = blockIdx.x * 128;

    // Load mapping: 128 rows x 32 halves = 512 16B chunks; 2 chunks/thread.
    const int lrow = tid >> 2;              // 0..63
    const int lch  = (tid & 3) * 8;         // half-col 0,8,16,24

    const uint32_t as_s = (uint32_t)__cvta_generic_to_shared(As);
    const uint32_t bs_s = (uint32_t)__cvta_generic_to_shared(Bs);
    const uint32_t bufB = GEMM_BUF * 2;     // bytes per stage

    // ldmatrix lane-address components
    const int aRowL = lane & 15;
    const int aColB = (lane >> 4) * 16;
    const int bRowL = (lane & 7) + ((lane >> 4) << 3);
    const int bColB = ((lane >> 3) & 1) * 16;
    const uint32_t aAddr0 = as_s + (uint32_t)((wm + aRowL) * GPH) * 2 + aColB;
    const uint32_t bAddr0 = bs_s + (uint32_t)((wn + bRowL) * GPH) * 2 + bColB;

    const int nt = K / 32;

    // Prologue: prefetch tiles 0 and 1
#pragma unroll
    for (int t = 0; t < 2; t++) {
        const uint32_t bo = t * bufB;
#pragma unroll
        for (int i = 0; i < 2; i++) {
            const int r = lrow + i * 64;
            const uint32_t so = bo + (uint32_t)(r * GPH + lch) * 2;
            cp16(as_s + so, A + (size_t)(bm + r) * K + t * 32 + lch);
            cp16(bs_s + so, Bm + (size_t)(bn + r) * K + t * 32 + lch);
        }
        cp_commit();
    }

    float acc[4][4][4];
#pragma unroll
    for (int i = 0; i < 4; i++)
#pragma unroll
        for (int j = 0; j < 4; j++)
#pragma unroll
            for (int r = 0; r < 4; r++) acc[i][j][r] = 0.0f;

    for (int it = 0; it < nt; it++) {
        if (it < nt - 1) cp_wait1(); else cp_wait0();
        __syncthreads();   // stage it ready; all warps done with stage (it-1)%3

        if (it + 2 < nt) {
            const uint32_t bo = (uint32_t)((it + 2) % GSTG) * bufB;
            const int kc = (it + 2) * 32;
#pragma unroll
            for (int i = 0; i < 2; i++) {
                const int r = lrow + i * 64;
                const uint32_t so = bo + (uint32_t)(r * GPH + lch) * 2;
                cp16(as_s + so, A + (size_t)(bm + r) * K + kc + lch);
                cp16(bs_s + so, Bm + (size_t)(bn + r) * K + kc + lch);
            }
            cp_commit();
        }

        const uint32_t sb = (uint32_t)(it % GSTG) * bufB;
        const uint32_t aB = aAddr0 + sb;
        const uint32_t bB = bAddr0 + sb;
#pragma unroll
        for (int ks = 0; ks < 2; ks++) {
            const uint32_t ko = (uint32_t)(ks * 32);    // 16 halves = 32B
            unsigned af[4][4];
#pragma unroll
            for (int mt = 0; mt < 4; mt++)
                ldsm_x4(af[mt][0], af[mt][1], af[mt][2], af[mt][3],
                        aB + (uint32_t)(mt * 16 * GPH) * 2 + ko);
            unsigned bf[4][2];
#pragma unroll
            for (int p = 0; p < 2; p++)
                ldsm_x4(bf[2 * p][0], bf[2 * p][1], bf[2 * p + 1][0], bf[2 * p + 1][1],
                        bB + (uint32_t)(p * 16 * GPH) * 2 + ko);
#pragma unroll
            for (int mt = 0; mt < 4; mt++)
#pragma unroll
                for (int nt2 = 0; nt2 < 4; nt2++)
                    mma_f16(acc[mt][nt2], af[mt][0], af[mt][1], af[mt][2], af[mt][3],
                            bf[nt2][0], bf[nt2][1]);
        }
    }

#pragma unroll
    for (int mt = 0; mt < 4; mt++) {
        const int r0 = bm + wm + mt * 16 + g;
#pragma unroll
        for (int nt2 = 0; nt2 < 4; nt2++) {
            const int c0 = bn + wn + nt2 * 8 + 2 * c;
            *(float2*)(Cm + (size_t)r0 * N + c0) = make_float2(acc[mt][nt2][0], acc[mt][nt2][1]);
            *(float2*)(Cm + (size_t)(r0 + 8) * N + c0) = make_float2(acc[mt][nt2][2], acc[mt][nt2][3]);
        }
    }
}

// ---------------------------------------------------------------------------
// RMSNorm(q,k) + RoPE + head-split into [B,H,T,D]; fp16 outputs.
// ---------------------------------------------------------------------------
__global__ void norm_rope_kernel(const float* __restrict__ qkv)
{
    const int lane = threadIdx.x;
    const int h = blockIdx.y * 4 + threadIdx.y;
    const int bt = blockIdx.x;
    const int b = bt / TT;
    const int t = bt % TT;

    const float* row = qkv + (size_t)bt * 3 * CC;
    float q0 = row[h * 64 + lane],           q1 = row[h * 64 + lane + 32];
    float k0 = row[CC + h * 64 + lane],      k1 = row[CC + h * 64 + lane + 32];
    float v0 = row[2 * CC + h * 64 + lane],  v1 = row[2 * CC + h * 64 + lane + 32];

    float qs = q0 * q0 + q1 * q1;
    float ks = k0 * k0 + k1 * k1;
#pragma unroll
    for (int w = 16; w >= 1; w >>= 1) {
        qs += __shfl_xor_sync(0xffffffffu, qs, w);
        ks += __shfl_xor_sync(0xffffffffu, ks, w);
    }
    const float eps = 1.1920929e-7f;
    float qr = rsqrtf(qs * (1.0f / 64.0f) + eps);
    float kr = rsqrtf(ks * (1.0f / 64.0f) + eps);
    q0 *= qr; q1 *= qr; k0 *= kr; k1 *= kr;

    float inv = powf(10000.0f, -(float)lane * (1.0f / 32.0f));
    float ang = (float)t * inv;
    float sn, cs;
    sincosf(ang, &sn, &cs);

    float qo0 = q0 * cs - q1 * sn;
    float qo1 = q1 * cs + q0 * sn;
    float ko0 = k0 * cs - k1 * sn;
    float ko1 = k1 * cs + k0 * sn;

    size_t o = (((size_t)b * HH + h) * TT + t) * DD;
    g_q[o + lane] = __float2half_rn(qo0); g_q[o + lane + 32] = __float2half_rn(qo1);
    g_k[o + lane] = __float2half_rn(ko0); g_k[o + lane + 32] = __float2half_rn(ko1);
    g_v[o + lane] = __float2half_rn(v0);  g_v[o + lane + 32] = __float2half_rn(v1);
}

// ---------------------------------------------------------------------------
// Causal flash attention, fp16 mma (m16n8k16), fp32 softmax/acc.
// 256 threads (8 warps), 128 q-rows/block, 64-key tiles.
// 3-stage cp.async K/V pipeline (2 groups in flight).
// Qs/Ps [128][72]h  — A-frags via ldmatrix.
// Ks    [3][64][72]h — S B-frags via ldmatrix.
// Vs    [3][64][72]h — PV B-frags via ldmatrix.trans.
// ---------------------------------------------------------------------------
#define FPH 72
#define FSTG 3
#define FBUF (64 * FPH)
#define FLASH_SMEM_BYTES ((128 * FPH + 2 * FSTG * FBUF) * 2)

__global__ __launch_bounds__(256) void flash_h()
{
    extern __shared__ __align__(16) __half smh[];
    __half* Ps  = smh;                        // [128][FPH]
    __half* KsB = smh + 128 * FPH;            // [FSTG][FBUF]
    __half* VsB = KsB + FSTG * FBUF;          // [FSTG][FBUF]

    const int tid  = threadIdx.x;
    const int warp = tid >> 5;
    const int lane = tid & 31;
    const int g = lane >> 2;
    const int c = lane & 3;
    const int qr = warp * 16;

    const int qt = gridDim.x - 1 - blockIdx.x;   // heavy tiles first
    const int bh = blockIdx.y;
    const int qbase = qt * 128;

    const __half* Q = g_q + (size_t)bh * TT * DD;
    const __half* K = g_k + (size_t)bh * TT * DD;
    const __half* V = g_v + (size_t)bh * TT * DD;

    // Stage Q tile [128][64]h into Ps
#pragma unroll
    for (int i = 0; i < 4; i++) {
        int idx = tid + i * 256;
        int r = idx >> 3, ch = (idx & 7) * 8;
        *(uint4*)&Ps[r * FPH + ch] = *(const uint4*)(Q + (size_t)(qbase + r) * 64 + ch);
    }

    const uint32_t ps_s = (uint32_t)__cvta_generic_to_shared(Ps);
    const uint32_t ks_s = (uint32_t)__cvta_generic_to_shared(KsB);
    const uint32_t vs_s = (uint32_t)__cvta_generic_to_shared(VsB);

    // ldmatrix lane-address components
    const int aRowL = lane & 15;
    const int aColB = (lane >> 4) * 16;
    const int bRowL = (lane & 7) + ((lane >> 4) << 3);
    const int bColB = ((lane >> 3) & 1) * 16;
    const uint32_t qAddr  = ps_s + (uint32_t)((qr + aRowL) * FPH) * 2 + aColB;  // Q/P A-frags
    const uint32_t kAddr0 = ks_s + (uint32_t)(bRowL * FPH) * 2 + bColB;         // K B-frags
    const uint32_t vAddr0 = vs_s + (uint32_t)(aRowL * FPH) * 2 + aColB;         // V B-frags (trans)

    const int nkt = 2 * qt + 2;
    const uint32_t bufB = (uint32_t)FBUF * 2;

    // Prologue: prefetch K/V tiles 0 and 1 (nkt >= 2 always)
#pragma unroll
    for (int t = 0; t < 2; t++) {
        const uint32_t bo = t * bufB;
#pragma unroll
        for (int i = 0; i < 2; i++) {
            int idx = tid + i * 256;
            int r = idx >> 3, ch = (idx & 7) * 8;
            cp16(ks_s + bo + (uint32_t)(r * FPH + ch) * 2, K + (size_t)(t * 64 + r) * 64 + ch);
            cp16(vs_s + bo + (uint32_t)(r * FPH + ch) * 2, V + (size_t)(t * 64 + r) * 64 + ch);
        }
        cp_commit();
    }
    __syncthreads();   // Q staging visible

    // Q A-fragments (4 k16-steps over d=64)
    unsigned qf[4][4];
#pragma unroll
    for (int ks = 0; ks < 4; ks++)
        ldsm_x4(qf[ks][0], qf[ks][1], qf[ks][2], qf[ks][3], qAddr + (uint32_t)(ks * 32));

    float oacc[8][4];
#pragma unroll
    for (int nt = 0; nt < 8; nt++)
#pragma unroll
        for (int r = 0; r < 4; r++) oacc[nt][r] = 0.0f;
    float m0 = -1e30f, m1 = -1e30f, l0 = 0.0f, l1 = 0.0f;

    const int ktmax_w = 2 * qt + (warp >= 4 ? 1 : 0);
    const int q0i = qbase + qr + g;
    const int q1i = q0i + 8;

    for (int kt = 0; kt < nkt; kt++) {
        if (kt < nkt - 1) cp_wait1(); else cp_wait0();
        __syncthreads();   // stage kt ready; all warps done with stage (kt-1)%3

        if (kt + 2 < nkt) {
            const int kb = (kt + 2) * 64;
            const uint32_t bo = (uint32_t)((kt + 2) % FSTG) * bufB;
#pragma unroll
            for (int i = 0; i < 2; i++) {
                int idx = tid + i * 256;
                int r = idx >> 3, ch = (idx & 7) * 8;
                cp16(ks_s + bo + (uint32_t)(r * FPH + ch) * 2, K + (size_t)(kb + r) * 64 + ch);
                cp16(vs_s + bo + (uint32_t)(r * FPH + ch) * 2, V + (size_t)(kb + r) * 64 + ch);
            }
            cp_commit();
        }

        if (kt > ktmax_w) continue;

        const uint32_t sb = (uint32_t)(kt % FSTG) * bufB;
        const uint32_t kB = kAddr0 + sb;
        const uint32_t vB = vAddr0 + sb;

        // S = Q K^T (4 k16-steps, 4 nt-pairs)
        float sacc[8][4];
#pragma unroll
        for (int nt = 0; nt < 8; nt++)
#pragma unroll
            for (int r = 0; r < 4; r++) sacc[nt][r] = 0.0f;

#pragma unroll
        for (int ks = 0; ks < 4; ks++) {
            const uint32_t ko = (uint32_t)(ks * 32);
#pragma unroll
            for (int p = 0; p < 4; p++) {
                unsigned b0a, b1a, b0b, b1b;
                ldsm_x4(b0a, b1a, b0b, b1b, kB + (uint32_t)(p * 16 * FPH) * 2 + ko);
                mma_f16(sacc[2 * p],     qf[ks][0], qf[ks][1], qf[ks][2], qf[ks][3], b0a, b1a);
                mma_f16(sacc[2 * p + 1], qf[ks][0], qf[ks][1], qf[ks][2], qf[ks][3], b0b, b1b);
            }
        }

        // scale + causal mask
        const bool diag = (kt >= 2 * qt);
#pragma unroll
        for (int nt = 0; nt < 8; nt++) {
#pragma unroll
            for (int r = 0; r < 4; r++) sacc[nt][r] *= 0.125f;
            if (diag) {
                const int key0 = kt * 64 + nt * 8 + 2 * c;
                if (key0 > q0i)     sacc[nt][0] = -1e30f;
                if (key0 + 1 > q0i) sacc[nt][1] = -1e30f;
                if (key0 > q1i)     sacc[nt][2] = -1e30f;
                if (key0 + 1 > q1i) sacc[nt][3] = -1e30f;
            }
        }

        // online softmax (quad reduction)
        float t0 = -1e30f, t1 = -1e30f;
#pragma unroll
        for (int nt = 0; nt < 8; nt++) {
            t0 = fmaxf(t0, fmaxf(sacc[nt][0], sacc[nt][1]));
            t1 = fmaxf(t1, fmaxf(sacc[nt][2], sacc[nt][3]));
        }
#pragma unroll
        for (int w = 1; w <= 2; w <<= 1) {
            t0 = fmaxf(t0, __shfl_xor_sync(0xffffffffu, t0, w));
            t1 = fmaxf(t1, __shfl_xor_sync(0xffffffffu, t1, w));
        }
        float mn0 = fmaxf(m0, t0), mn1 = fmaxf(m1, t1);
        float al0 = __expf(m0 - mn0), al1 = __expf(m1 - mn1);
        m0 = mn0; m1 = mn1;

        float rs0 = 0.0f, rs1 = 0.0f;
        __syncwarp();   // prior PV A-frag reads of Ps done (warp-private rows)
#pragma unroll
        for (int nt = 0; nt < 8; nt++) {
            float p0 = __expf(sacc[nt][0] - m0);
            float p1 = __expf(sacc[nt][1] - m0);
            float p2 = __expf(sacc[nt][2] - m1);
            float p3 = __expf(sacc[nt][3] - m1);
            rs0 += p0 + p1; rs1 += p2 + p3;
            const int col = nt * 8 + 2 * c;
            *(__half2*)&Ps[(qr + g) * FPH + col]     = __floats2half2_rn(p0, p1);
            *(__half2*)&Ps[(qr + g + 8) * FPH + col] = __floats2half2_rn(p2, p3);
        }
#pragma unroll
        for (int w = 1; w <= 2; w <<= 1) {
            rs0 += __shfl_xor_sync(0xffffffffu, rs0, w);
            rs1 += __shfl_xor_sync(0xffffffffu, rs1, w);
        }
        l0 = l0 * al0 + rs0;
        l1 = l1 * al1 + rs1;
#pragma unroll
        for (int nt = 0; nt < 8; nt++) {
            oacc[nt][0] *= al0; oacc[nt][1] *= al0;
            oacc[nt][2] *= al1; oacc[nt][3] *= al1;
        }
        __syncwarp();   // P visible to whole warp

        // O += P V (P A-frags ldmatrix; V B-frags ldmatrix.trans)
#pragma unroll
        for (int ks = 0; ks < 4; ks++) {
            const uint32_t kro = (uint32_t)(ks * 16 * FPH) * 2;   // 16-key group
            unsigned pf0, pf1, pf2, pf3;
            ldsm_x4(pf0, pf1, pf2, pf3, qAddr + (uint32_t)(ks * 32));
#pragma unroll
            for (int p = 0; p < 4; p++) {
                unsigned b0a, b1a, b0b, b1b;
                ldsm_x4_t(b0a, b1a, b0b, b1b, vB + kro + (uint32_t)(p * 32));
                mma_f16(oacc[2 * p],     pf0, pf1, pf2, pf3, b0a, b1a);
                mma_f16(oacc[2 * p + 1], pf0, pf1, pf2, pf3, b0b, b1b);
            }
        }
    }

    // Epilogue: normalize, fp16-round (GEMM2 consumes y), scatter heads
    const int b = bh / HH;
    const int h = bh % HH;
    const float inv0 = 1.0f / l0, inv1 = 1.0f / l1;
    const int row0 = qbase + qr + g;
#pragma unroll
    for (int nt = 0; nt < 8; nt++) {
        const int col = h * 64 + nt * 8 + 2 * c;
        *(__half2*)(g_y + (size_t)(b * TT + row0) * CC + col) =
            __floats2half2_rn(oacc[nt][0] * inv0, oacc[nt][1] * inv0);
        *(__half2*)(g_y + (size_t)(b * TT + row0 + 8) * CC + col) =
            __floats2half2_rn(oacc[nt][2] * inv1, oacc[nt][3] * inv1);
    }
}

// ---------------------------------------------------------------------------
extern "C" void kernel_launch(void* const* d_in, const int* in_sizes, int n_in,
                              void* d_out, int out_size)
{
    const float* x      = (const float*)d_in[0];
    const float* w_attn = (const float*)d_in[1];
    const float* w_proj = (const float*)d_in[2];
    float* out = (float*)d_out;

    float *qkv;
    __half *y, *xr, *war, *wpr;
    cudaGetSymbolAddress((void**)&qkv, g_qkv);
    cudaGetSymbolAddress((void**)&y,   g_y);
    cudaGetSymbolAddress((void**)&xr,  g_xr);
    cudaGetSymbolAddress((void**)&war, g_war);
    cudaGetSymbolAddress((void**)&wpr, g_wpr);

    // 0) RN-round all GEMM inputs to fp16 (single launch)
    {
        const int total4 = N4_X + N4_WA + N4_WP;
        round_all_kernel<<<(total4 + 255) / 256, 256>>>(
            (const float4*)x, (__half2*)xr,
            (const float4*)w_attn, (__half2*)war,
            (const float4*)w_proj, (__half2*)wpr);
    }

    // 1) QKV projection: [4096,3072]
    cudaFuncSetAttribute(hgemm_abt, cudaFuncAttributeMaxDynamicSharedMemorySize,
                         GEMM_SMEM_BYTES);
    hgemm_abt<<<dim3(3 * CC / 128, BB * TT / 128), 256, GEMM_SMEM_BYTES>>>(
        xr, war, qkv, BB * TT, 3 * CC, CC);

    // 2) RMSNorm + RoPE + head split (fp16 outputs)
    norm_rope_kernel<<<dim3(BB * TT, HH / 4), dim3(32, 4)>>>(qkv);

    // 3) Causal flash attention (fp16 MMA)
    cudaFuncSetAttribute(flash_h, cudaFuncAttributeMaxDynamicSharedMemorySize,
                         FLASH_SMEM_BYTES);
    flash_h<<<dim3(TT / 128, BB * HH), 256, FLASH_SMEM_BYTES>>>();

    // 4) Output projection: [4096,1024]
    hgemm_abt<<<dim3(CC / 128, BB * TT / 128), 256, GEMM_SMEM_BYTES>>>(
        y, wpr, out, BB * TT, CC, CC);
}